// round 8
// baseline (speedup 1.0000x reference)
#include <cuda_runtime.h>
#include <cstdint>

#define D_MODEL  4096
#define REMAINED 4403
#define BATCH    32

#define SPLITK   8
#define KSPLIT   (D_MODEL / SPLITK)     // 512
#define KC       64                     // k per chunk
#define NCHUNK   (KSPLIT / KC)          // 8
#define MTILE    128
#define NBLKM    ((REMAINED + MTILE - 1) / MTILE)   // 35
#define THREADS  256

#define OUT_ELEMS (BATCH * REMAINED)    // 140896

// padded rows: 72 bf16 (144 B) -> conflict-free STS/ldmatrix (proven in R7)
#define RSTR     72
#define RSTRB    (RSTR * 2)
// one buffer: w_hi | w_lo | x_hi | x_lo
#define B_WHI    0
#define B_WLO    (B_WHI + MTILE * RSTRB)    // 18432
#define B_XHI    (B_WLO + MTILE * RSTRB)    // 36864
#define B_XLO    (B_XHI + BATCH * RSTRB)    // 41472
#define BUF_SZ   (B_XLO + BATCH * RSTRB)    // 46080
#define SM_TOTAL (2 * BUF_SZ)               // 92160 (dynamic)

__device__ float g_scratch[(size_t)SPLITK * OUT_ELEMS];   // ~4.5 MB
__device__ int   g_cnt[NBLKM];                            // zero-init, self-resetting

// ---------------- helpers ----------------
__device__ __forceinline__ uint32_t smem_u32(const void* p) {
    uint32_t a;
    asm("{ .reg .u64 t; cvta.to.shared.u64 t, %1; cvt.u32.u64 %0, t; }" : "=r"(a) : "l"(p));
    return a;
}
__device__ __forceinline__ uint32_t pack_hi(float a, float b) {
    uint32_t r;
    asm("prmt.b32 %0, %1, %2, 0x7632;" : "=r"(r)
        : "r"(__float_as_uint(a)), "r"(__float_as_uint(b)));
    return r;
}
__device__ __forceinline__ float hi_f(float v) {
    return __uint_as_float(__float_as_uint(v) & 0xFFFF0000u);
}
__device__ __forceinline__ uint32_t pack_lo(float e0, float e1) {
    uint32_t r;
    asm("cvt.rn.bf16x2.f32 %0, %1, %2;" : "=r"(r) : "f"(e1), "f"(e0));
    return r;
}
__device__ __forceinline__ void ldm_x4(uint32_t* r, uint32_t addr) {
    asm volatile("ldmatrix.sync.aligned.m8n8.x4.shared.b16 {%0,%1,%2,%3}, [%4];"
        : "=r"(r[0]), "=r"(r[1]), "=r"(r[2]), "=r"(r[3]) : "r"(addr));
}
__device__ __forceinline__ void mma_bf16(float* c, const uint32_t* a, const uint32_t* b) {
    asm volatile("mma.sync.aligned.m16n8k16.row.col.f32.bf16.bf16.f32 "
        "{%0,%1,%2,%3}, {%4,%5,%6,%7}, {%8,%9}, {%0,%1,%2,%3};"
        : "+f"(c[0]), "+f"(c[1]), "+f"(c[2]), "+f"(c[3])
        : "r"(a[0]), "r"(a[1]), "r"(a[2]), "r"(a[3]), "r"(b[0]), "r"(b[1]));
}
__device__ __forceinline__ void split_store(char* base_hi, char* base_lo,
                                            uint32_t off, float4 v) {
    uint32_t h0 = pack_hi(v.x, v.y);
    uint32_t h1 = pack_hi(v.z, v.w);
    float l0 = v.x - hi_f(v.x), l1 = v.y - hi_f(v.y);
    float l2 = v.z - hi_f(v.z), l3 = v.w - hi_f(v.w);
    *(uint2*)(base_hi + off) = make_uint2(h0, h1);
    *(uint2*)(base_lo + off) = make_uint2(pack_lo(l0, l1), pack_lo(l2, l3));
}

// ---------------- fused GEMM + split-K reduce ----------------
__global__ void __launch_bounds__(THREADS, 2)
gemm_bf16x3(const float* __restrict__ x,      // [32, 4096]
            const float* __restrict__ w,      // [11008, 4096]
            const int*   __restrict__ idx,    // [4403]
            float*       __restrict__ out)    // [32, 4403]
{
    extern __shared__ __align__(16) char smem[];
    __shared__ int s_last;

    const int tid   = threadIdx.x;
    const int lane  = tid & 31;
    const int wq    = tid >> 5;
    const int mg    = wq >> 1;            // m-group 0..3 (32 rows)
    const int ng    = wq & 1;             // n-group 0..1 (16 batch)
    const int mbase = blockIdx.x * MTILE;
    const int k0    = blockIdx.y * KSPLIT;

    // ---- gmem load geometry ----
    const int wrow = tid >> 1;
    const int wseg = (tid & 1) * 32;
    int gn = mbase + wrow; if (gn >= REMAINED) gn = REMAINED - 1;
    const float4* wp = (const float4*)(w + (size_t)idx[gn] * D_MODEL + k0 + wseg);
    const int xrow = tid & 31;
    const int xseg = (tid >> 5) * 8;
    const float4* xp = (const float4*)(x + (size_t)xrow * D_MODEL + k0 + xseg);

    const uint32_t w_sts = (uint32_t)(wrow * RSTRB + wseg * 2);
    const uint32_t x_sts = (uint32_t)(xrow * RSTRB + xseg * 2);

    // ---- ldmatrix base offsets (per-buffer-relative) ----
    const uint32_t a_row = (uint32_t)(mg * 32 + (lane & 15));
    const uint32_t a_off = a_row * RSTRB + (lane >> 4) * 16;
    const uint32_t b_row = (uint32_t)(ng * 16 + (lane & 7) + ((lane >> 4) << 3));
    const uint32_t b_off = b_row * RSTRB + ((lane >> 3) & 1) * 16;
    const uint32_t sb = smem_u32(smem);

    float acc[2][2][4];
#pragma unroll
    for (int s = 0; s < 2; s++)
#pragma unroll
        for (int n = 0; n < 2; n++)
#pragma unroll
            for (int r = 0; r < 4; r++) acc[s][n][r] = 0.f;

    // prefetch chunk 0
    float4 pw[8], px[2];
#pragma unroll
    for (int i = 0; i < 8; i++) pw[i] = wp[i];
#pragma unroll
    for (int i = 0; i < 2; i++) px[i] = xp[i];

#pragma unroll 1
    for (int c = 0; c < NCHUNK; c++) {
        char* buf = smem + (c & 1) * BUF_SZ;

        // STS chunk c (overlaps other warps' MMA of chunk c-1)
#pragma unroll
        for (int i = 0; i < 8; i++)
            split_store(buf + B_WHI, buf + B_WLO, w_sts + i * 8, pw[i]);
#pragma unroll
        for (int i = 0; i < 2; i++)
            split_store(buf + B_XHI, buf + B_XLO, x_sts + i * 8, px[i]);

        // issue chunk c+1 loads (hidden under MMA below)
        if (c + 1 < NCHUNK) {
            const int o4 = (c + 1) * (KC / 4);
#pragma unroll
            for (int i = 0; i < 8; i++) pw[i] = wp[o4 + i];
#pragma unroll
            for (int i = 0; i < 2; i++) px[i] = xp[o4 + i];
        }

        __syncthreads();

        const uint32_t bsb = sb + (uint32_t)((c & 1) * BUF_SZ);
#pragma unroll
        for (int ks = 0; ks < 4; ks++) {
            const uint32_t ka = (uint32_t)(ks * 32);
            uint32_t ahi[2][4], alo[2][4], bhi[4], blo[4];
#pragma unroll
            for (int s = 0; s < 2; s++) {
                uint32_t ao = a_off + (uint32_t)(s * 16 * RSTRB) + ka;
                ldm_x4(ahi[s], bsb + B_WHI + ao);
                ldm_x4(alo[s], bsb + B_WLO + ao);
            }
            ldm_x4(bhi, bsb + B_XHI + b_off + ka);
            ldm_x4(blo, bsb + B_XLO + b_off + ka);

#pragma unroll
            for (int s = 0; s < 2; s++)
#pragma unroll
                for (int n = 0; n < 2; n++) {
                    mma_bf16(acc[s][n], ahi[s], bhi + 2 * n);
                    mma_bf16(acc[s][n], ahi[s], blo + 2 * n);
                    mma_bf16(acc[s][n], alo[s], bhi + 2 * n);
                }
        }
    }

    // ---- epilogue: scatter to split scratch ----
    float* scr = g_scratch + (size_t)blockIdx.y * OUT_ELEMS;
#pragma unroll
    for (int s = 0; s < 2; s++) {
        const int n_row0 = mbase + mg * 32 + s * 16 + (lane >> 2);
#pragma unroll
        for (int n = 0; n < 2; n++) {
            const int b0 = ng * 16 + n * 8 + 2 * (lane & 3);
            if (n_row0 < REMAINED) {
                scr[(size_t)(b0 + 0) * REMAINED + n_row0] = acc[s][n][0];
                scr[(size_t)(b0 + 1) * REMAINED + n_row0] = acc[s][n][1];
            }
            if (n_row0 + 8 < REMAINED) {
                scr[(size_t)(b0 + 0) * REMAINED + n_row0 + 8] = acc[s][n][2];
                scr[(size_t)(b0 + 1) * REMAINED + n_row0 + 8] = acc[s][n][3];
            }
        }
    }

    // ---- fused deterministic reduce: last CTA of this m-tile sums 8 splits ----
    __threadfence();
    __syncthreads();
    if (tid == 0) s_last = atomicAdd(&g_cnt[blockIdx.x], 1);
    __syncthreads();
    if (s_last == SPLITK - 1) {
        __threadfence();
#pragma unroll 1
        for (int it = 0; it < (MTILE * BATCH) / THREADS; it++) {
            const int e = it * THREADS + tid;
            const int b = e >> 7;                 // 0..31
            const int n = mbase + (e & 127);
            if (n < REMAINED) {
                const size_t o = (size_t)b * REMAINED + n;
                float s = 0.f;
#pragma unroll
                for (int sp = 0; sp < SPLITK; sp++)
                    s += g_scratch[(size_t)sp * OUT_ELEMS + o];
                out[o] = s;
            }
        }
        if (tid == 0) g_cnt[blockIdx.x] = 0;      // reset for next graph replay
    }
}

extern "C" void kernel_launch(void* const* d_in, const int* in_sizes, int n_in,
                              void* d_out, int out_size) {
    const float* x   = (const float*)d_in[0];
    const float* w   = (const float*)d_in[1];
    const int*   idx = (const int*)d_in[2];
    float*       out = (float*)d_out;

    static bool configured = false;
    if (!configured) {
        cudaFuncSetAttribute(gemm_bf16x3,
                             cudaFuncAttributeMaxDynamicSharedMemorySize, SM_TOTAL);
        configured = true;
    }

    dim3 grid(NBLKM, SPLITK);                 // 35 x 8 = 280 CTAs (2/SM, one wave)
    gemm_bf16x3<<<grid, THREADS, SM_TOTAL>>>(x, w, idx, out);
}

// round 11
// speedup vs baseline: 1.4858x; 1.4858x over previous
#include <cuda_runtime.h>
#include <cstdint>

#define D_MODEL  4096
#define REMAINED 4403
#define BATCH    32

#define SPLITK   8
#define KSPLIT   (D_MODEL / SPLITK)     // 512
#define KC       64                     // k per chunk
#define NCHUNK   (KSPLIT / KC)          // 8
#define MTILE    128
#define NBLKM    ((REMAINED + MTILE - 1) / MTILE)   // 35
#define THREADS  256

#define OUT_ELEMS (BATCH * REMAINED)    // 140896

// padded rows: 72 bf16 (144 B) -> conflict-free ldmatrix (proven R7/R8)
#define RSTR     72
#define RSTRB    (RSTR * 2)
#define B_WHI    0
#define B_WLO    (B_WHI + MTILE * RSTRB)    // 18432
#define B_XHI    (B_WLO + MTILE * RSTRB)    // 36864
#define B_XLO    (B_XHI + BATCH * RSTRB)    // 41472
#define BUF_SZ   (B_XLO + BATCH * RSTRB)    // 46080
#define SM_TOTAL (2 * BUF_SZ)               // 92160 dynamic

__device__ float g_scratch[(size_t)SPLITK * OUT_ELEMS];   // ~4.5 MB
__device__ int   g_cnt[NBLKM];                            // zero-init, self-resetting

// ---------------- helpers ----------------
__device__ __forceinline__ uint32_t smem_u32(const void* p) {
    uint32_t a;
    asm("{ .reg .u64 t; cvta.to.shared.u64 t, %1; cvt.u32.u64 %0, t; }" : "=r"(a) : "l"(p));
    return a;
}
__device__ __forceinline__ uint32_t pack_hi(float a, float b) {
    uint32_t r;
    asm("prmt.b32 %0, %1, %2, 0x7632;" : "=r"(r)
        : "r"(__float_as_uint(a)), "r"(__float_as_uint(b)));
    return r;
}
__device__ __forceinline__ float hi_f(float v) {
    return __uint_as_float(__float_as_uint(v) & 0xFFFF0000u);
}
__device__ __forceinline__ uint32_t pack_lo(float e0, float e1) {
    uint32_t r;
    asm("cvt.rn.bf16x2.f32 %0, %1, %2;" : "=r"(r) : "f"(e1), "f"(e0));
    return r;
}
__device__ __forceinline__ void ldm_x4(uint32_t* r, uint32_t addr) {
    asm volatile("ldmatrix.sync.aligned.m8n8.x4.shared.b16 {%0,%1,%2,%3}, [%4];"
        : "=r"(r[0]), "=r"(r[1]), "=r"(r[2]), "=r"(r[3]) : "r"(addr));
}
__device__ __forceinline__ void mma_bf16(float* c, const uint32_t* a, const uint32_t* b) {
    asm volatile("mma.sync.aligned.m16n8k16.row.col.f32.bf16.bf16.f32 "
        "{%0,%1,%2,%3}, {%4,%5,%6,%7}, {%8,%9}, {%0,%1,%2,%3};"
        : "+f"(c[0]), "+f"(c[1]), "+f"(c[2]), "+f"(c[3])
        : "r"(a[0]), "r"(a[1]), "r"(a[2]), "r"(a[3]), "r"(b[0]), "r"(b[1]));
}
// two adjacent float4 (8 consecutive fp32) -> 16B hi + 16B lo STS.128
__device__ __forceinline__ void split_store16(char* base_hi, char* base_lo,
                                              uint32_t off, float4 v0, float4 v1) {
    uint4 h = make_uint4(pack_hi(v0.x, v0.y), pack_hi(v0.z, v0.w),
                         pack_hi(v1.x, v1.y), pack_hi(v1.z, v1.w));
    uint4 e = make_uint4(pack_lo(v0.x - hi_f(v0.x), v0.y - hi_f(v0.y)),
                         pack_lo(v0.z - hi_f(v0.z), v0.w - hi_f(v0.w)),
                         pack_lo(v1.x - hi_f(v1.x), v1.y - hi_f(v1.y)),
                         pack_lo(v1.z - hi_f(v1.z), v1.w - hi_f(v1.w)));
    *(uint4*)(base_hi + off) = h;
    *(uint4*)(base_lo + off) = e;
}

// ---------------- fused GEMM + split-K reduce ----------------
__global__ void __launch_bounds__(THREADS, 2)
gemm_bf16x3(const float* __restrict__ x,      // [32, 4096]
            const float* __restrict__ w,      // [11008, 4096]
            const int*   __restrict__ idx,    // [4403]
            float*       __restrict__ out)    // [32, 4403]
{
    extern __shared__ __align__(16) char smem[];
    __shared__ int s_last;

    const int tid   = threadIdx.x;
    const int lane  = tid & 31;
    const int wq    = tid >> 5;
    const int mg    = wq >> 1;            // m-group 0..3
    const int ng    = wq & 1;             // n-group 0..1
    const int mbase = blockIdx.x * MTILE;
    const int k0    = blockIdx.y * KSPLIT;

    const int lr = lane >> 3;             // row-sub 0..3
    const int lc = lane & 7;              // 16B-unit / 32B-column 0..7

    // ---- gmem load geometry: 4 w rows + 1 x row per thread ----
    const float* wptr[4];
    uint32_t w_sts[4];
#pragma unroll
    for (int j = 0; j < 4; j++) {
        const int rloc = wq * 16 + j * 4 + lr;         // 0..127
        int gn = mbase + rloc; if (gn >= REMAINED) gn = REMAINED - 1;
        wptr[j]  = w + (size_t)idx[gn] * D_MODEL + k0 + lc * 8;
        w_sts[j] = (uint32_t)(rloc * RSTRB + lc * 16);
    }
    const int xrloc = wq * 4 + lr;                     // 0..31
    const float* xptr = x + (size_t)xrloc * D_MODEL + k0 + lc * 8;
    const uint32_t x_sts = (uint32_t)(xrloc * RSTRB + lc * 16);

    // ---- ldmatrix base offsets (unchanged from R8, proven) ----
    const uint32_t a_row = (uint32_t)(mg * 32 + (lane & 15));
    const uint32_t a_off = a_row * RSTRB + (lane >> 4) * 16;
    const uint32_t b_row = (uint32_t)(ng * 16 + (lane & 7) + ((lane >> 4) << 3));
    const uint32_t b_off = b_row * RSTRB + ((lane >> 3) & 1) * 16;
    const uint32_t sb = smem_u32(smem);

    float acc[2][2][4];
#pragma unroll
    for (int s = 0; s < 2; s++)
#pragma unroll
        for (int n = 0; n < 2; n++)
#pragma unroll
            for (int r = 0; r < 4; r++) acc[s][n][r] = 0.f;

    // prefetch chunk 0
    float4 pw[8], px[2];
#pragma unroll
    for (int j = 0; j < 4; j++) {
        pw[2 * j + 0] = *(const float4*)(wptr[j] + 0);
        pw[2 * j + 1] = *(const float4*)(wptr[j] + 4);
    }
    px[0] = *(const float4*)(xptr + 0);
    px[1] = *(const float4*)(xptr + 4);

#pragma unroll 1
    for (int c = 0; c < NCHUNK; c++) {
        char* buf = smem + (c & 1) * BUF_SZ;

        // STS chunk c (conflict-free 16B stores)
#pragma unroll
        for (int j = 0; j < 4; j++)
            split_store16(buf + B_WHI, buf + B_WLO, w_sts[j], pw[2 * j], pw[2 * j + 1]);
        split_store16(buf + B_XHI, buf + B_XLO, x_sts, px[0], px[1]);

        // issue chunk c+1 loads (hidden under MMA below)
        if (c + 1 < NCHUNK) {
            const int ko = (c + 1) * KC;
#pragma unroll
            for (int j = 0; j < 4; j++) {
                pw[2 * j + 0] = *(const float4*)(wptr[j] + ko + 0);
                pw[2 * j + 1] = *(const float4*)(wptr[j] + ko + 4);
            }
            px[0] = *(const float4*)(xptr + ko + 0);
            px[1] = *(const float4*)(xptr + ko + 4);
        }

        __syncthreads();

        const uint32_t bsb = sb + (uint32_t)((c & 1) * BUF_SZ);
#pragma unroll
        for (int ks = 0; ks < 4; ks++) {
            const uint32_t ka = (uint32_t)(ks * 32);
            uint32_t ahi[2][4], alo[2][4], bhi[4], blo[4];
#pragma unroll
            for (int s = 0; s < 2; s++) {
                uint32_t ao = a_off + (uint32_t)(s * 16 * RSTRB) + ka;
                ldm_x4(ahi[s], bsb + B_WHI + ao);
                ldm_x4(alo[s], bsb + B_WLO + ao);
            }
            ldm_x4(bhi, bsb + B_XHI + b_off + ka);
            ldm_x4(blo, bsb + B_XLO + b_off + ka);

#pragma unroll
            for (int s = 0; s < 2; s++)
#pragma unroll
                for (int n = 0; n < 2; n++) {
                    mma_bf16(acc[s][n], ahi[s], bhi + 2 * n);
                    mma_bf16(acc[s][n], ahi[s], blo + 2 * n);
                    mma_bf16(acc[s][n], alo[s], bhi + 2 * n);
                }
        }
        if (c + 2 <= NCHUNK) __syncthreads();   // free buffer for next STS round
    }

    // ---- epilogue: scatter to split scratch ----
    float* scr = g_scratch + (size_t)blockIdx.y * OUT_ELEMS;
#pragma unroll
    for (int s = 0; s < 2; s++) {
        const int n_row0 = mbase + mg * 32 + s * 16 + (lane >> 2);
#pragma unroll
        for (int n = 0; n < 2; n++) {
            const int b0 = ng * 16 + n * 8 + 2 * (lane & 3);
            if (n_row0 < REMAINED) {
                scr[(size_t)(b0 + 0) * REMAINED + n_row0] = acc[s][n][0];
                scr[(size_t)(b0 + 1) * REMAINED + n_row0] = acc[s][n][1];
            }
            if (n_row0 + 8 < REMAINED) {
                scr[(size_t)(b0 + 0) * REMAINED + n_row0 + 8] = acc[s][n][2];
                scr[(size_t)(b0 + 1) * REMAINED + n_row0 + 8] = acc[s][n][3];
            }
        }
    }

    // ---- fused deterministic reduce: last CTA of this m-tile sums 8 splits ----
    __threadfence();
    __syncthreads();
    if (tid == 0) s_last = atomicAdd(&g_cnt[blockIdx.x], 1);
    __syncthreads();
    if (s_last == SPLITK - 1) {
        __threadfence();
#pragma unroll 1
        for (int it = 0; it < (MTILE * BATCH) / THREADS; it++) {
            const int e = it * THREADS + tid;
            const int b = e >> 7;
            const int n = mbase + (e & 127);
            if (n < REMAINED) {
                const size_t o = (size_t)b * REMAINED + n;
                float s = 0.f;
#pragma unroll
                for (int sp = 0; sp < SPLITK; sp++)
                    s += g_scratch[(size_t)sp * OUT_ELEMS + o];
                out[o] = s;
            }
        }
        if (tid == 0) g_cnt[blockIdx.x] = 0;
    }
}

extern "C" void kernel_launch(void* const* d_in, const int* in_sizes, int n_in,
                              void* d_out, int out_size) {
    const float* x   = (const float*)d_in[0];
    const float* w   = (const float*)d_in[1];
    const int*   idx = (const int*)d_in[2];
    float*       out = (float*)d_out;

    static bool configured = false;
    if (!configured) {
        cudaFuncSetAttribute(gemm_bf16x3,
                             cudaFuncAttributeMaxDynamicSharedMemorySize, SM_TOTAL);
        configured = true;
    }

    dim3 grid(NBLKM, SPLITK);                 // 35 x 8 = 280 CTAs (2/SM)
    gemm_bf16x3<<<grid, THREADS, SM_TOTAL>>>(x, w, idx, out);
}